// round 3
// baseline (speedup 1.0000x reference)
#include <cuda_runtime.h>
#include <cuda_bf16.h>
#include <cstdint>

#define BB 64
#define SS 128
#define TT 32
#define HH 1024
#define VV 32000
#define K3 (3*HH)
#define G4 (4*HH)

// ---------------- device scratch (static; no allocations allowed) ----------------
__device__ __nv_bfloat16 g_boutW[(size_t)VV*HH];     // 65.5 MB  (logits weights, bf16)
__device__ float         g_Wcat[(size_t)G4*K3];      // 50 MB    [W_ih | W_hh] fp32
__device__ float         g_keys[SS*HH];
__device__ float         g_qw1[BB*HH];
__device__ float         g_h[BB*HH];
__device__ float         g_c[BB*HH];
__device__ float         g_x3[BB*K3];                // [emb | ctx | h] fp32
__device__ float         g_gates[BB*G4];
__device__ __nv_bfloat16 g_Habf[(size_t)BB*TT*HH];   // [b][t][h] for logits GEMM
__device__ float         g_gbias[G4];

// ---------------- helpers ----------------
__device__ __forceinline__ void mma16816(float* c, const uint32_t* a, const uint32_t* b) {
    asm volatile(
        "mma.sync.aligned.m16n8k16.row.col.f32.bf16.bf16.f32 "
        "{%0,%1,%2,%3}, {%4,%5,%6,%7}, {%8,%9}, {%0,%1,%2,%3};\n"
        : "+f"(c[0]), "+f"(c[1]), "+f"(c[2]), "+f"(c[3])
        : "r"(a[0]), "r"(a[1]), "r"(a[2]), "r"(a[3]), "r"(b[0]), "r"(b[1]));
}

__device__ __forceinline__ void mma1688_tf32(float* c, const uint32_t* a, const uint32_t* b) {
    asm volatile(
        "mma.sync.aligned.m16n8k8.row.col.f32.tf32.tf32.f32 "
        "{%0,%1,%2,%3}, {%4,%5,%6,%7}, {%8,%9}, {%0,%1,%2,%3};\n"
        : "+f"(c[0]), "+f"(c[1]), "+f"(c[2]), "+f"(c[3])
        : "r"(a[0]), "r"(a[1]), "r"(a[2]), "r"(a[3]), "r"(b[0]), "r"(b[1]));
}

__device__ __forceinline__ float to_tf32(float x) {
    uint32_t u;
    asm("cvt.rna.tf32.f32 %0, %1;" : "=r"(u) : "f"(x));
    return __uint_as_float(u);
}

__device__ __forceinline__ float tanh_fast(float x) {
    float y;
    asm("tanh.approx.f32 %0, %1;" : "=f"(y) : "f"(x));
    return y;
}

// ---------------- prep kernels ----------------
__global__ void k_cvt(const float* __restrict__ src, __nv_bfloat16* __restrict__ dst, size_t n) {
    size_t i = (size_t)blockIdx.x * blockDim.x + threadIdx.x;
    size_t stride = (size_t)gridDim.x * blockDim.x;
    for (; i < n; i += stride) dst[i] = __float2bfloat16(src[i]);
}

__global__ void k_wcat(const float* __restrict__ Wih, const float* __restrict__ Whh) {
    size_t total = (size_t)G4 * K3;
    size_t i = (size_t)blockIdx.x * blockDim.x + threadIdx.x;
    size_t stride = (size_t)gridDim.x * blockDim.x;
    for (; i < total; i += stride) {
        int gg = (int)(i / K3), k = (int)(i % K3);
        g_Wcat[i] = (k < 2 * HH) ? Wih[(size_t)gg * (2 * HH) + k]
                                 : Whh[(size_t)gg * HH + (k - 2 * HH)];
    }
}

__global__ void k_gbias(const float* __restrict__ bih, const float* __restrict__ bhh) {
    int i = blockIdx.x * blockDim.x + threadIdx.x;
    if (i < G4) g_gbias[i] = bih[i] + bhh[i];
}

// ---------------- tf32 tensor-core GEMM: C[M,N] = A[M,K] @ W[N,K]^T + bias ----------------
// BM=64, BN=64, BK=32, 128 threads (4 warps 2x2), warp tile 32x32
__global__ void __launch_bounds__(128) k_gemm32(
    const float* __restrict__ A,
    const float* __restrict__ W,
    const float* __restrict__ bias,
    float* __restrict__ C,
    int M, int N, int K)
{
    __shared__ float As[64][36];
    __shared__ float Ws[64][36];
    int tid = threadIdx.x;
    int warp = tid >> 5, lane = tid & 31;
    int gid = lane >> 2, t4 = lane & 3;
    int wm = warp & 1, wn = warp >> 1;
    int m0 = blockIdx.y * 64;
    int n0 = blockIdx.x * 64;

    float acc[2][4][4] = {};

    int lrow = tid >> 1;          // 0..63
    int lcol = (tid & 1) * 16;    // 0 or 16

    const float* gA = A + (size_t)(m0 + lrow) * K + lcol;
    const float* gW = W + (size_t)(n0 + lrow) * K + lcol;

    for (int k0 = 0; k0 < K; k0 += 32) {
        #pragma unroll
        for (int q = 0; q < 16; q += 4) {
            float4 va = *reinterpret_cast<const float4*>(gA + k0 + q);
            float4 vw = *reinterpret_cast<const float4*>(gW + k0 + q);
            As[lrow][lcol + q]     = to_tf32(va.x);
            As[lrow][lcol + q + 1] = to_tf32(va.y);
            As[lrow][lcol + q + 2] = to_tf32(va.z);
            As[lrow][lcol + q + 3] = to_tf32(va.w);
            Ws[lrow][lcol + q]     = to_tf32(vw.x);
            Ws[lrow][lcol + q + 1] = to_tf32(vw.y);
            Ws[lrow][lcol + q + 2] = to_tf32(vw.z);
            Ws[lrow][lcol + q + 3] = to_tf32(vw.w);
        }
        __syncthreads();

        #pragma unroll
        for (int kk = 0; kk < 32; kk += 8) {
            uint32_t afrag[2][4], bfrag[4][2];
            #pragma unroll
            for (int mi = 0; mi < 2; mi++) {
                int r = wm * 32 + mi * 16 + gid;
                afrag[mi][0] = __float_as_uint(As[r][kk + t4]);
                afrag[mi][1] = __float_as_uint(As[r + 8][kk + t4]);
                afrag[mi][2] = __float_as_uint(As[r][kk + t4 + 4]);
                afrag[mi][3] = __float_as_uint(As[r + 8][kk + t4 + 4]);
            }
            #pragma unroll
            for (int ni = 0; ni < 4; ni++) {
                int n = wn * 32 + ni * 8 + gid;
                bfrag[ni][0] = __float_as_uint(Ws[n][kk + t4]);
                bfrag[ni][1] = __float_as_uint(Ws[n][kk + t4 + 4]);
            }
            #pragma unroll
            for (int mi = 0; mi < 2; mi++)
                #pragma unroll
                for (int ni = 0; ni < 4; ni++)
                    mma1688_tf32(acc[mi][ni], afrag[mi], bfrag[ni]);
        }
        __syncthreads();
    }

    #pragma unroll
    for (int mi = 0; mi < 2; mi++) {
        int r = m0 + wm * 32 + mi * 16 + gid;
        #pragma unroll
        for (int ni = 0; ni < 4; ni++) {
            int cb = n0 + wn * 32 + ni * 8 + 2 * t4;
            float b0 = bias ? bias[cb] : 0.f;
            float b1 = bias ? bias[cb + 1] : 0.f;
            C[(size_t)r * N + cb]           = acc[mi][ni][0] + b0;
            C[(size_t)r * N + cb + 1]       = acc[mi][ni][1] + b1;
            C[(size_t)(r + 8) * N + cb]     = acc[mi][ni][2] + b0;
            C[(size_t)(r + 8) * N + cb + 1] = acc[mi][ni][3] + b1;
        }
    }
}

// ---------------- bf16 tensor-core GEMM (logits only) ----------------
__global__ void __launch_bounds__(128) k_gemm(
    const __nv_bfloat16* __restrict__ A,
    const __nv_bfloat16* __restrict__ W,
    const float* __restrict__ bias,
    float* __restrict__ C,
    int M, int N, int K)
{
    __shared__ __nv_bfloat16 As[64][48];
    __shared__ __nv_bfloat16 Ws[64][48];
    int tid = threadIdx.x;
    int warp = tid >> 5, lane = tid & 31;
    int gid = lane >> 2, t4 = lane & 3;
    int wm = warp & 1, wn = warp >> 1;
    int m0 = blockIdx.y * 64;
    int n0 = blockIdx.x * 64;

    float acc[2][4][4] = {};

    int lrow = tid >> 1;
    int lcol = (tid & 1) * 16;

    const __nv_bfloat16* gA = A + (size_t)(m0 + lrow) * K + lcol;
    const __nv_bfloat16* gW = W + (size_t)(n0 + lrow) * K + lcol;

    for (int k0 = 0; k0 < K; k0 += 32) {
        uint4 va0 = *reinterpret_cast<const uint4*>(gA + k0);
        uint4 va1 = *reinterpret_cast<const uint4*>(gA + k0 + 8);
        uint4 vw0 = *reinterpret_cast<const uint4*>(gW + k0);
        uint4 vw1 = *reinterpret_cast<const uint4*>(gW + k0 + 8);
        *reinterpret_cast<uint4*>(&As[lrow][lcol])     = va0;
        *reinterpret_cast<uint4*>(&As[lrow][lcol + 8]) = va1;
        *reinterpret_cast<uint4*>(&Ws[lrow][lcol])     = vw0;
        *reinterpret_cast<uint4*>(&Ws[lrow][lcol + 8]) = vw1;
        __syncthreads();

        #pragma unroll
        for (int kk = 0; kk < 32; kk += 16) {
            uint32_t afrag[2][4], bfrag[4][2];
            #pragma unroll
            for (int mi = 0; mi < 2; mi++) {
                int r = wm * 32 + mi * 16 + gid;
                afrag[mi][0] = *reinterpret_cast<const uint32_t*>(&As[r][kk + 2 * t4]);
                afrag[mi][1] = *reinterpret_cast<const uint32_t*>(&As[r + 8][kk + 2 * t4]);
                afrag[mi][2] = *reinterpret_cast<const uint32_t*>(&As[r][kk + 2 * t4 + 8]);
                afrag[mi][3] = *reinterpret_cast<const uint32_t*>(&As[r + 8][kk + 2 * t4 + 8]);
            }
            #pragma unroll
            for (int ni = 0; ni < 4; ni++) {
                int n = wn * 32 + ni * 8 + gid;
                bfrag[ni][0] = *reinterpret_cast<const uint32_t*>(&Ws[n][kk + 2 * t4]);
                bfrag[ni][1] = *reinterpret_cast<const uint32_t*>(&Ws[n][kk + 2 * t4 + 8]);
            }
            #pragma unroll
            for (int mi = 0; mi < 2; mi++)
                #pragma unroll
                for (int ni = 0; ni < 4; ni++)
                    mma16816(acc[mi][ni], afrag[mi], bfrag[ni]);
        }
        __syncthreads();
    }

    #pragma unroll
    for (int mi = 0; mi < 2; mi++) {
        int r = m0 + wm * 32 + mi * 16 + gid;
        #pragma unroll
        for (int ni = 0; ni < 4; ni++) {
            int cb = n0 + wn * 32 + ni * 8 + 2 * t4;
            float b0 = bias ? bias[cb] : 0.f;
            float b1 = bias ? bias[cb + 1] : 0.f;
            C[(size_t)r * N + cb]           = acc[mi][ni][0] + b0;
            C[(size_t)r * N + cb + 1]       = acc[mi][ni][1] + b1;
            C[(size_t)(r + 8) * N + cb]     = acc[mi][ni][2] + b0;
            C[(size_t)(r + 8) * N + cb + 1] = acc[mi][ni][3] + b1;
        }
    }
}

// ---------------- fused attention: scores + softmax + context + x3 build ----------------
__global__ void __launch_bounds__(256) k_attn(
    const float* __restrict__ enc,   // (B,S,H)
    const float* __restrict__ emb,   // (V,H)
    const int*   __restrict__ target,// (B,T)
    const float* __restrict__ Vw,    // (H)
    const float* __restrict__ Vb,    // (1)
    float* __restrict__ attn_out,    // (T,B,S)
    int t)
{
    __shared__ float q[HH];
    __shared__ float vw[HH];
    __shared__ float sc[SS];
    __shared__ float red[128];
    int b = blockIdx.x;
    int tid = threadIdx.x;

    for (int j = tid; j < HH; j += 256) { q[j] = g_qw1[b * HH + j]; vw[j] = Vw[j]; }
    __syncthreads();

    int warp = tid >> 5, lane = tid & 31;
    for (int s = warp; s < SS; s += 8) {
        const float* kp = &g_keys[s * HH];
        float p = 0.f;
        for (int j = lane; j < HH; j += 32)
            p = fmaf(vw[j], tanh_fast(q[j] + kp[j]), p);
        #pragma unroll
        for (int o = 16; o; o >>= 1) p += __shfl_xor_sync(0xffffffffu, p, o);
        if (lane == 0) sc[s] = p + Vb[0];
    }
    __syncthreads();

    if (tid < 128) red[tid] = sc[tid];
    __syncthreads();
    for (int w = 64; w > 0; w >>= 1) {
        if (tid < w) red[tid] = fmaxf(red[tid], red[tid + w]);
        __syncthreads();
    }
    float mx = red[0];
    __syncthreads();
    if (tid < 128) { float e = __expf(sc[tid] - mx); sc[tid] = e; red[tid] = e; }
    __syncthreads();
    for (int w = 64; w > 0; w >>= 1) {
        if (tid < w) red[tid] += red[tid + w];
        __syncthreads();
    }
    float inv = 1.f / red[0];
    if (tid < 128) {
        float a = sc[tid] * inv;
        sc[tid] = a;
        attn_out[((size_t)t * BB + b) * SS + tid] = a;
    }
    __syncthreads();

    for (int j = tid; j < HH; j += 256) {
        const float* ep = enc + (size_t)b * SS * HH + j;
        float a0 = 0.f, a1 = 0.f, a2 = 0.f, a3 = 0.f;
        #pragma unroll 4
        for (int s = 0; s < SS; s += 4) {
            a0 = fmaf(sc[s],     ep[(size_t)s * HH],       a0);
            a1 = fmaf(sc[s + 1], ep[(size_t)(s + 1) * HH], a1);
            a2 = fmaf(sc[s + 2], ep[(size_t)(s + 2) * HH], a2);
            a3 = fmaf(sc[s + 3], ep[(size_t)(s + 3) * HH], a3);
        }
        g_x3[b * K3 + HH + j] = (a0 + a1) + (a2 + a3);
    }

    int tok = target[b * TT + t];
    const float* er = emb + (size_t)tok * HH;
    for (int j = tid; j < HH; j += 256)
        g_x3[b * K3 + j] = er[j];
}

// ---------------- LSTM cell ----------------
__global__ void k_cell(int t) {
    int idx = blockIdx.x * blockDim.x + threadIdx.x;
    if (idx >= BB * HH) return;
    int b = idx / HH, h = idx % HH;
    const float* gp = &g_gates[b * G4];
    float gi = gp[h], gf = gp[HH + h], gg = gp[2 * HH + h], go = gp[3 * HH + h];
    float si = 1.f / (1.f + __expf(-gi));
    float sf = 1.f / (1.f + __expf(-gf));
    float so = 1.f / (1.f + __expf(-go));
    float cn = sf * g_c[idx] + si * tanhf(gg);
    float hn = so * tanhf(cn);
    g_c[idx] = cn;
    g_h[idx] = hn;
    g_x3[b * K3 + 2 * HH + h] = hn;
    g_Habf[((size_t)b * TT + t) * HH + h] = __float2bfloat16(hn);
}

__global__ void k_seed() {
    int idx = blockIdx.x * blockDim.x + threadIdx.x;
    if (idx >= BB * HH) return;
    int b = idx / HH, h = idx % HH;
    g_x3[b * K3 + 2 * HH + h] = g_h[idx];
}

__global__ void k_copyhc(float* __restrict__ oh, float* __restrict__ oc) {
    int idx = blockIdx.x * blockDim.x + threadIdx.x;
    if (idx >= BB * HH) return;
    oh[idx] = g_h[idx];
    oc[idx] = g_c[idx];
}

// ---------------- fused log-softmax over V ----------------
__global__ void __launch_bounds__(256) k_logsoftmax(float* __restrict__ logits) {
    int r = blockIdx.x;
    float* row = logits + (size_t)r * VV;
    float m = -1e30f, s = 0.f;
    for (int v = threadIdx.x; v < VV; v += 256) {
        float x = row[v];
        float nm = fmaxf(m, x);
        s = s * __expf(m - nm) + __expf(x - nm);
        m = nm;
    }
    __shared__ float sm[256], ssum[256];
    sm[threadIdx.x] = m; ssum[threadIdx.x] = s;
    __syncthreads();
    for (int w = 128; w > 0; w >>= 1) {
        if (threadIdx.x < w) {
            float m1 = sm[threadIdx.x], s1 = ssum[threadIdx.x];
            float m2 = sm[threadIdx.x + w], s2 = ssum[threadIdx.x + w];
            float nm = fmaxf(m1, m2);
            sm[threadIdx.x] = nm;
            ssum[threadIdx.x] = s1 * __expf(m1 - nm) + s2 * __expf(m2 - nm);
        }
        __syncthreads();
    }
    float lse = sm[0] + __logf(ssum[0]);
    for (int v = threadIdx.x; v < VV; v += 256) row[v] -= lse;
}

// ---------------- host launch ----------------
static void launch_gemm32(const float* A, const float* W, const float* bias,
                          float* C, int M, int N, int K) {
    dim3 grid(N / 64, M / 64);
    k_gemm32<<<grid, 128>>>(A, W, bias, C, M, N, K);
}

extern "C" void kernel_launch(void* const* d_in, const int* in_sizes, int n_in,
                              void* d_out, int out_size) {
    (void)in_sizes; (void)n_in; (void)out_size;
    const float* enc    = (const float*)d_in[0];
    const float* encH   = (const float*)d_in[1];
    const float* encC   = (const float*)d_in[2];
    const int*   target = (const int*)d_in[4];
    const float* emb    = (const float*)d_in[5];
    const float* W1     = (const float*)d_in[6];
    const float* b1     = (const float*)d_in[7];
    const float* W2     = (const float*)d_in[8];
    const float* b2     = (const float*)d_in[9];
    const float* Vw     = (const float*)d_in[10];
    const float* Vb     = (const float*)d_in[11];
    const float* Wih    = (const float*)d_in[12];
    const float* Whh    = (const float*)d_in[13];
    const float* bih    = (const float*)d_in[14];
    const float* bhh    = (const float*)d_in[15];
    const float* outW   = (const float*)d_in[16];
    const float* outb   = (const float*)d_in[17];
    const float* br1W   = (const float*)d_in[18];
    const float* br1b   = (const float*)d_in[19];
    const float* br2W   = (const float*)d_in[20];
    const float* br2b   = (const float*)d_in[21];

    float* out = (float*)d_out;
    float* out_logp = out;                                  // (B,T,V)
    float* out_h    = out + (size_t)BB * TT * VV;           // (1,B,H)
    float* out_c    = out_h + BB * HH;                      // (1,B,H)
    float* out_attn = out_c + BB * HH;                      // (T,B,S)

    void *pboutW, *pkeys, *pqw1, *ph, *pc, *px3, *pgates, *pHabf, *pgbias, *pWcat;
    cudaGetSymbolAddress(&pboutW, g_boutW);
    cudaGetSymbolAddress(&pkeys, g_keys);
    cudaGetSymbolAddress(&pqw1, g_qw1);
    cudaGetSymbolAddress(&ph, g_h);
    cudaGetSymbolAddress(&pc, g_c);
    cudaGetSymbolAddress(&px3, g_x3);
    cudaGetSymbolAddress(&pgates, g_gates);
    cudaGetSymbolAddress(&pHabf, g_Habf);
    cudaGetSymbolAddress(&pgbias, g_gbias);
    cudaGetSymbolAddress(&pWcat, g_Wcat);

    // prep
    k_cvt<<<4096, 256>>>(outW, (__nv_bfloat16*)pboutW, (size_t)VV * HH);
    k_wcat<<<4096, 256>>>(Wih, Whh);
    k_gbias<<<(G4 + 255) / 256, 256>>>(bih, bhh);

    // bridge + keys (tf32, fp32 in/out)
    launch_gemm32(encH, br1W, br1b, (float*)ph,    BB, HH, HH);
    launch_gemm32(encC, br2W, br2b, (float*)pc,    BB, HH, HH);
    launch_gemm32(enc,  W2,   b2,   (float*)pkeys, SS, HH, HH);   // encoder_outputs[0]
    k_seed<<<BB * HH / 256, 256>>>();

    // recurrent steps
    for (int t = 0; t < TT; t++) {
        launch_gemm32((float*)ph, W1, b1, (float*)pqw1, BB, HH, HH);
        k_attn<<<BB, 256>>>(enc, emb, target, Vw, Vb, out_attn, t);
        launch_gemm32((float*)px3, (float*)pWcat, (float*)pgbias,
                      (float*)pgates, BB, G4, K3);
        k_cell<<<BB * HH / 256, 256>>>(t);
    }

    k_copyhc<<<BB * HH / 256, 256>>>(out_h, out_c);

    // big logits GEMM (bf16) + log-softmax in place
    {
        dim3 grid(VV / 64, BB * TT / 64);
        k_gemm<<<grid, 128>>>((__nv_bfloat16*)pHabf, (__nv_bfloat16*)pboutW, outb,
                              out_logp, BB * TT, VV, HH);
    }
    k_logsoftmax<<<BB * TT, 256>>>(out_logp);
}

// round 5
// speedup vs baseline: 2.1066x; 2.1066x over previous
#include <cuda_runtime.h>
#include <cuda_bf16.h>
#include <cstdint>

#define BB 64
#define SS 128
#define TT 32
#define HH 1024
#define VV 32000
#define G4 (4*HH)
#define K2 (2*HH)

#define NSTAGE 3
#define BKQ 32
#define SMEM_DYN (NSTAGE*64*36*2*sizeof(float))   // 55296 B

// ---------------- device scratch ----------------
__device__ __nv_bfloat16 g_boutW[(size_t)VV*HH];      // logits weights bf16
__device__ float g_Wcat2[(size_t)G4*K2];              // interleaved [Wih_ctx | Whh], tf32-rounded
__device__ float g_WihE[(size_t)G4*HH];               // interleaved Wih emb part, tf32-rounded
__device__ float g_embE[(size_t)TT*BB*G4];            // E[t][b][n] = emb@WihE^T + gbias
__device__ float g_embA[(size_t)TT*BB*HH];            // gathered emb rows, tf32-rounded
__device__ float g_W1t[HH*HH];                        // W1 tf32-rounded
__device__ float g_rW[HH*HH];                         // reusable rounded weight
__device__ float g_rA[SS*HH];                         // reusable rounded activation
__device__ float g_keys[SS*HH];
__device__ float g_qw1[BB*HH];
__device__ float g_h[BB*HH];
__device__ float g_c[BB*HH];
__device__ float g_htf[BB*HH];                        // tf32-rounded h (GEMM A)
__device__ float g_x2[2][BB*K2];                      // double-buffered [ctx | h], tf32-rounded
__device__ __nv_bfloat16 g_Habf[(size_t)BB*TT*HH];
__device__ float g_gbiasp[G4];                        // permuted b_ih+b_hh

// ---------------- helpers ----------------
__device__ __forceinline__ void mma16816(float* c, const uint32_t* a, const uint32_t* b) {
    asm volatile(
        "mma.sync.aligned.m16n8k16.row.col.f32.bf16.bf16.f32 "
        "{%0,%1,%2,%3}, {%4,%5,%6,%7}, {%8,%9}, {%0,%1,%2,%3};\n"
        : "+f"(c[0]), "+f"(c[1]), "+f"(c[2]), "+f"(c[3])
        : "r"(a[0]), "r"(a[1]), "r"(a[2]), "r"(a[3]), "r"(b[0]), "r"(b[1]));
}
__device__ __forceinline__ void mma1688_tf32(float* c, const uint32_t* a, const uint32_t* b) {
    asm volatile(
        "mma.sync.aligned.m16n8k8.row.col.f32.tf32.tf32.f32 "
        "{%0,%1,%2,%3}, {%4,%5,%6,%7}, {%8,%9}, {%0,%1,%2,%3};\n"
        : "+f"(c[0]), "+f"(c[1]), "+f"(c[2]), "+f"(c[3])
        : "r"(a[0]), "r"(a[1]), "r"(a[2]), "r"(a[3]), "r"(b[0]), "r"(b[1]));
}
__device__ __forceinline__ float to_tf32(float x) {
    uint32_t u;
    asm("cvt.rna.tf32.f32 %0, %1;" : "=r"(u) : "f"(x));
    return __uint_as_float(u);
}
__device__ __forceinline__ float tanh_fast(float x) {
    float y;
    asm("tanh.approx.f32 %0, %1;" : "=f"(y) : "f"(x));
    return y;
}
__device__ __forceinline__ void cp16(float* smem, const float* gmem) {
    uint32_t s = (uint32_t)__cvta_generic_to_shared(smem);
    asm volatile("cp.async.ca.shared.global [%0], [%1], 16;\n" :: "r"(s), "l"(gmem));
}
#define CP_COMMIT asm volatile("cp.async.commit_group;\n" ::: "memory")
#define CP_WAIT1  asm volatile("cp.async.wait_group 1;\n" ::: "memory")

// ---------------- prep kernels ----------------
__global__ void k_cvt(const float* __restrict__ src, __nv_bfloat16* __restrict__ dst, size_t n) {
    size_t i = (size_t)blockIdx.x * blockDim.x + threadIdx.x;
    size_t stride = (size_t)gridDim.x * blockDim.x;
    for (; i < n; i += stride) dst[i] = __float2bfloat16(src[i]);
}
__global__ void k_round(const float* __restrict__ src, float* __restrict__ dst, size_t n) {
    size_t i = (size_t)blockIdx.x * blockDim.x + threadIdx.x;
    size_t stride = (size_t)gridDim.x * blockDim.x;
    for (; i < n; i += stride) dst[i] = to_tf32(src[i]);
}
// Wcat2[r=4h+g][c] : c<H -> Wih[g*H+h][H+c] (ctx part); else Whh[g*H+h][c-H]
__global__ void k_wcat2(const float* __restrict__ Wih, const float* __restrict__ Whh) {
    size_t total = (size_t)G4 * K2;
    size_t i = (size_t)blockIdx.x * blockDim.x + threadIdx.x;
    size_t stride = (size_t)gridDim.x * blockDim.x;
    for (; i < total; i += stride) {
        int r = (int)(i / K2), c = (int)(i % K2);
        int h = r >> 2, g = r & 3;
        int orig = g * HH + h;
        float v = (c < HH) ? Wih[(size_t)orig * K2 + HH + c]
                           : Whh[(size_t)orig * HH + (c - HH)];
        g_Wcat2[i] = to_tf32(v);
    }
}
__global__ void k_wembE(const float* __restrict__ Wih) {
    size_t total = (size_t)G4 * HH;
    size_t i = (size_t)blockIdx.x * blockDim.x + threadIdx.x;
    size_t stride = (size_t)gridDim.x * blockDim.x;
    for (; i < total; i += stride) {
        int r = (int)(i / HH), c = (int)(i % HH);
        int h = r >> 2, g = r & 3;
        g_WihE[i] = to_tf32(Wih[(size_t)(g * HH + h) * K2 + c]);
    }
}
__global__ void k_gbiasp(const float* __restrict__ bih, const float* __restrict__ bhh) {
    int r = blockIdx.x * blockDim.x + threadIdx.x;
    if (r >= G4) return;
    int h = r >> 2, g = r & 3;
    g_gbiasp[r] = bih[g * HH + h] + bhh[g * HH + h];
}
// gathered emb rows: row m = t*BB+b -> emb[target[b][t]], tf32-rounded
__global__ void k_embA(const float* __restrict__ emb, const int* __restrict__ target) {
    size_t total = (size_t)TT * BB * HH;
    size_t i = (size_t)blockIdx.x * blockDim.x + threadIdx.x;
    size_t stride = (size_t)gridDim.x * blockDim.x;
    for (; i < total; i += stride) {
        int m = (int)(i / HH), j = (int)(i % HH);
        int t = m >> 6, b = m & 63;
        int tok = target[b * TT + t];
        g_embA[i] = to_tf32(emb[(size_t)tok * HH + j]);
    }
}

// ---------------- pipelined tf32 GEMM pieces ----------------
__device__ __forceinline__ void gemm_load_stage(
    float* As, float* Ws, const float* gA, const float* gW, int K, int k0, int tid)
{
    #pragma unroll
    for (int i = 0; i < 4; i++) {
        int c = tid + i * 128;
        int row = c >> 3, col = (c & 7) << 2;
        cp16(As + row * 36 + col, gA + (size_t)row * K + k0 + col);
        cp16(Ws + row * 36 + col, gW + (size_t)row * K + k0 + col);
    }
    CP_COMMIT;
}

__device__ __forceinline__ void gemm_compute_stage(
    const float* As, const float* Ws, float acc[2][4][4],
    int wm, int wn, int gid, int t4)
{
    #pragma unroll
    for (int kk = 0; kk < 32; kk += 8) {
        uint32_t afrag[2][4], bfrag[4][2];
        #pragma unroll
        for (int mi = 0; mi < 2; mi++) {
            int r = wm * 32 + mi * 16 + gid;
            afrag[mi][0] = __float_as_uint(As[r * 36 + kk + t4]);
            afrag[mi][1] = __float_as_uint(As[(r + 8) * 36 + kk + t4]);
            afrag[mi][2] = __float_as_uint(As[r * 36 + kk + t4 + 4]);
            afrag[mi][3] = __float_as_uint(As[(r + 8) * 36 + kk + t4 + 4]);
        }
        #pragma unroll
        for (int ni = 0; ni < 4; ni++) {
            int n = wn * 32 + ni * 8 + gid;
            bfrag[ni][0] = __float_as_uint(Ws[n * 36 + kk + t4]);
            bfrag[ni][1] = __float_as_uint(Ws[n * 36 + kk + t4 + 4]);
        }
        #pragma unroll
        for (int mi = 0; mi < 2; mi++)
            #pragma unroll
            for (int ni = 0; ni < 4; ni++)
                mma1688_tf32(acc[mi][ni], afrag[mi], bfrag[ni]);
    }
}

__global__ void __launch_bounds__(128) k_gemm_t(
    const float* __restrict__ A, const float* __restrict__ W,
    const float* __restrict__ bias, float* __restrict__ C,
    int M, int N, int K)
{
    extern __shared__ float sm[];
    float* AsB = sm;
    float* WsB = sm + NSTAGE * 64 * 36;
    int tid = threadIdx.x;
    int warp = tid >> 5, lane = tid & 31;
    int gid = lane >> 2, t4 = lane & 3;
    int wm = warp & 1, wn = warp >> 1;
    int m0 = blockIdx.y * 64, n0 = blockIdx.x * 64;
    const float* gA = A + (size_t)m0 * K;
    const float* gW = W + (size_t)n0 * K;

    float acc[2][4][4] = {};
    int KT = K / BKQ;

    gemm_load_stage(AsB, WsB, gA, gW, K, 0, tid);
    gemm_load_stage(AsB + 64*36, WsB + 64*36, gA, gW, K, BKQ, tid);

    for (int kt = 0; kt < KT; kt++) {
        CP_WAIT1;
        __syncthreads();
        int s = kt % NSTAGE;
        gemm_compute_stage(AsB + s*64*36, WsB + s*64*36, acc, wm, wn, gid, t4);
        int kn = kt + 2;
        if (kn < KT) {
            int sn = kn % NSTAGE;
            gemm_load_stage(AsB + sn*64*36, WsB + sn*64*36, gA, gW, K, kn * BKQ, tid);
        } else {
            CP_COMMIT;
        }
    }

    #pragma unroll
    for (int mi = 0; mi < 2; mi++) {
        int r = m0 + wm * 32 + mi * 16 + gid;
        #pragma unroll
        for (int ni = 0; ni < 4; ni++) {
            int cb = n0 + wn * 32 + ni * 8 + 2 * t4;
            float b0 = bias ? bias[cb] : 0.f;
            float b1 = bias ? bias[cb + 1] : 0.f;
            C[(size_t)r * N + cb]           = acc[mi][ni][0] + b0;
            C[(size_t)r * N + cb + 1]       = acc[mi][ni][1] + b1;
            C[(size_t)(r + 8) * N + cb]     = acc[mi][ni][2] + b0;
            C[(size_t)(r + 8) * N + cb + 1] = acc[mi][ni][3] + b1;
        }
    }
}

// ---------------- gates GEMM (K=2048) with fused LSTM cell epilogue ----------------
// Reads x2 buf[t&1]; writes new h into buf[(t+1)&1] (no same-launch WAR race).
__global__ void __launch_bounds__(128) k_gates(int t) {
    extern __shared__ float sm[];
    __shared__ float sg[64][68];
    float* AsB = sm;
    float* WsB = sm + NSTAGE * 64 * 36;
    int tid = threadIdx.x;
    int warp = tid >> 5, lane = tid & 31;
    int gid = lane >> 2, t4 = lane & 3;
    int wm = warp & 1, wn = warp >> 1;
    int n0 = blockIdx.x * 64;
    const float* gA = g_x2[t & 1];
    const float* gW = g_Wcat2 + (size_t)n0 * K2;

    float acc[2][4][4] = {};
    const int KT = K2 / BKQ;   // 64

    gemm_load_stage(AsB, WsB, gA, gW, K2, 0, tid);
    gemm_load_stage(AsB + 64*36, WsB + 64*36, gA, gW, K2, BKQ, tid);

    for (int kt = 0; kt < KT; kt++) {
        CP_WAIT1;
        __syncthreads();
        int s = kt % NSTAGE;
        gemm_compute_stage(AsB + s*64*36, WsB + s*64*36, acc, wm, wn, gid, t4);
        int kn = kt + 2;
        if (kn < KT) {
            int sn = kn % NSTAGE;
            gemm_load_stage(AsB + sn*64*36, WsB + sn*64*36, gA, gW, K2, kn * BKQ, tid);
        } else {
            CP_COMMIT;
        }
    }

    // accumulators + E -> smem gate tile
    const float* E = g_embE + (size_t)t * BB * G4;
    #pragma unroll
    for (int mi = 0; mi < 2; mi++) {
        int r = wm * 32 + mi * 16 + gid;
        #pragma unroll
        for (int ni = 0; ni < 4; ni++) {
            int cb = wn * 32 + ni * 8 + 2 * t4;
            int n = n0 + cb;
            sg[r][cb]       = acc[mi][ni][0] + E[(size_t)r * G4 + n];
            sg[r][cb + 1]   = acc[mi][ni][1] + E[(size_t)r * G4 + n + 1];
            sg[r+8][cb]     = acc[mi][ni][2] + E[(size_t)(r+8) * G4 + n];
            sg[r+8][cb + 1] = acc[mi][ni][3] + E[(size_t)(r+8) * G4 + n + 1];
        }
    }
    __syncthreads();

    // fused LSTM cell: this tile covers h in [n0/4, n0/4+16), all 64 batches
    float* x2next = g_x2[(t + 1) & 1];
    int hloc = tid & 15, b0 = tid >> 4;
    int hbase = n0 >> 2;
    #pragma unroll
    for (int pass = 0; pass < 8; pass++) {
        int b = b0 + pass * 8;
        float gi = sg[b][4 * hloc];
        float gf = sg[b][4 * hloc + 1];
        float gg = sg[b][4 * hloc + 2];
        float go = sg[b][4 * hloc + 3];
        int h = hbase + hloc;
        int idx = b * HH + h;
        float si = 1.f / (1.f + __expf(-gi));
        float sf = 1.f / (1.f + __expf(-gf));
        float so = 1.f / (1.f + __expf(-go));
        float cn = sf * g_c[idx] + si * tanhf(gg);
        float hn = so * tanhf(cn);
        g_c[idx] = cn;
        g_h[idx] = hn;
        float ht = to_tf32(hn);
        g_htf[idx] = ht;
        x2next[b * K2 + HH + h] = ht;
        g_Habf[((size_t)b * TT + t) * HH + h] = __float2bfloat16(hn);
    }
}

// ---------------- bf16 tensor-core GEMM (logits) ----------------
__global__ void __launch_bounds__(128) k_gemm(
    const __nv_bfloat16* __restrict__ A,
    const __nv_bfloat16* __restrict__ W,
    const float* __restrict__ bias,
    float* __restrict__ C,
    int M, int N, int K)
{
    __shared__ __nv_bfloat16 As[64][48];
    __shared__ __nv_bfloat16 Ws[64][48];
    int tid = threadIdx.x;
    int warp = tid >> 5, lane = tid & 31;
    int gid = lane >> 2, t4 = lane & 3;
    int wm = warp & 1, wn = warp >> 1;
    int m0 = blockIdx.y * 64;
    int n0 = blockIdx.x * 64;

    float acc[2][4][4] = {};
    int lrow = tid >> 1;
    int lcol = (tid & 1) * 16;
    const __nv_bfloat16* gA = A + (size_t)(m0 + lrow) * K + lcol;
    const __nv_bfloat16* gW = W + (size_t)(n0 + lrow) * K + lcol;

    for (int k0 = 0; k0 < K; k0 += 32) {
        uint4 va0 = *reinterpret_cast<const uint4*>(gA + k0);
        uint4 va1 = *reinterpret_cast<const uint4*>(gA + k0 + 8);
        uint4 vw0 = *reinterpret_cast<const uint4*>(gW + k0);
        uint4 vw1 = *reinterpret_cast<const uint4*>(gW + k0 + 8);
        *reinterpret_cast<uint4*>(&As[lrow][lcol])     = va0;
        *reinterpret_cast<uint4*>(&As[lrow][lcol + 8]) = va1;
        *reinterpret_cast<uint4*>(&Ws[lrow][lcol])     = vw0;
        *reinterpret_cast<uint4*>(&Ws[lrow][lcol + 8]) = vw1;
        __syncthreads();

        #pragma unroll
        for (int kk = 0; kk < 32; kk += 16) {
            uint32_t afrag[2][4], bfrag[4][2];
            #pragma unroll
            for (int mi = 0; mi < 2; mi++) {
                int r = wm * 32 + mi * 16 + gid;
                afrag[mi][0] = *reinterpret_cast<const uint32_t*>(&As[r][kk + 2 * t4]);
                afrag[mi][1] = *reinterpret_cast<const uint32_t*>(&As[r + 8][kk + 2 * t4]);
                afrag[mi][2] = *reinterpret_cast<const uint32_t*>(&As[r][kk + 2 * t4 + 8]);
                afrag[mi][3] = *reinterpret_cast<const uint32_t*>(&As[r + 8][kk + 2 * t4 + 8]);
            }
            #pragma unroll
            for (int ni = 0; ni < 4; ni++) {
                int n = wn * 32 + ni * 8 + gid;
                bfrag[ni][0] = *reinterpret_cast<const uint32_t*>(&Ws[n][kk + 2 * t4]);
                bfrag[ni][1] = *reinterpret_cast<const uint32_t*>(&Ws[n][kk + 2 * t4 + 8]);
            }
            #pragma unroll
            for (int mi = 0; mi < 2; mi++)
                #pragma unroll
                for (int ni = 0; ni < 4; ni++)
                    mma16816(acc[mi][ni], afrag[mi], bfrag[ni]);
        }
        __syncthreads();
    }

    #pragma unroll
    for (int mi = 0; mi < 2; mi++) {
        int r = m0 + wm * 32 + mi * 16 + gid;
        #pragma unroll
        for (int ni = 0; ni < 4; ni++) {
            int cb = n0 + wn * 32 + ni * 8 + 2 * t4;
            float b0 = bias ? bias[cb] : 0.f;
            float b1 = bias ? bias[cb + 1] : 0.f;
            C[(size_t)r * N + cb]           = acc[mi][ni][0] + b0;
            C[(size_t)r * N + cb + 1]       = acc[mi][ni][1] + b1;
            C[(size_t)(r + 8) * N + cb]     = acc[mi][ni][2] + b0;
            C[(size_t)(r + 8) * N + cb + 1] = acc[mi][ni][3] + b1;
        }
    }
}

// ---------------- fused attention ----------------
__global__ void __launch_bounds__(256) k_attn(
    const float* __restrict__ enc,
    const float* __restrict__ Vw,
    const float* __restrict__ Vb,
    float* __restrict__ attn_out,
    int t)
{
    __shared__ float q[HH];
    __shared__ float vw[HH];
    __shared__ float sc[SS];
    __shared__ float red[128];
    int b = blockIdx.x;
    int tid = threadIdx.x;

    for (int j = tid; j < HH; j += 256) { q[j] = g_qw1[b * HH + j]; vw[j] = Vw[j]; }
    __syncthreads();

    int warp = tid >> 5, lane = tid & 31;
    for (int s = warp; s < SS; s += 8) {
        const float* kp = &g_keys[s * HH];
        float p = 0.f;
        for (int j = lane; j < HH; j += 32)
            p = fmaf(vw[j], tanh_fast(q[j] + kp[j]), p);
        #pragma unroll
        for (int o = 16; o; o >>= 1) p += __shfl_xor_sync(0xffffffffu, p, o);
        if (lane == 0) sc[s] = p + Vb[0];
    }
    __syncthreads();

    if (tid < 128) red[tid] = sc[tid];
    __syncthreads();
    for (int w = 64; w > 0; w >>= 1) {
        if (tid < w) red[tid] = fmaxf(red[tid], red[tid + w]);
        __syncthreads();
    }
    float mx = red[0];
    __syncthreads();
    if (tid < 128) { float e = __expf(sc[tid] - mx); sc[tid] = e; red[tid] = e; }
    __syncthreads();
    for (int w = 64; w > 0; w >>= 1) {
        if (tid < w) red[tid] += red[tid + w];
        __syncthreads();
    }
    float inv = 1.f / red[0];
    if (tid < 128) {
        float a = sc[tid] * inv;
        sc[tid] = a;
        attn_out[((size_t)t * BB + b) * SS + tid] = a;
    }
    __syncthreads();

    float* x2cur = g_x2[t & 1];
    for (int j = tid; j < HH; j += 256) {
        const float* ep = enc + (size_t)b * SS * HH + j;
        float a0 = 0.f, a1 = 0.f, a2 = 0.f, a3 = 0.f;
        #pragma unroll 4
        for (int s = 0; s < SS; s += 4) {
            a0 = fmaf(sc[s],     ep[(size_t)s * HH],       a0);
            a1 = fmaf(sc[s + 1], ep[(size_t)(s + 1) * HH], a1);
            a2 = fmaf(sc[s + 2], ep[(size_t)(s + 2) * HH], a2);
            a3 = fmaf(sc[s + 3], ep[(size_t)(s + 3) * HH], a3);
        }
        x2cur[b * K2 + j] = to_tf32((a0 + a1) + (a2 + a3));
    }
}

// ---------------- misc small kernels ----------------
__global__ void k_seed() {
    int idx = blockIdx.x * blockDim.x + threadIdx.x;
    if (idx >= BB * HH) return;
    int b = idx / HH, h = idx % HH;
    float ht = to_tf32(g_h[idx]);
    g_htf[idx] = ht;
    g_x2[0][b * K2 + HH + h] = ht;
}
__global__ void k_copyhc(float* __restrict__ oh, float* __restrict__ oc) {
    int idx = blockIdx.x * blockDim.x + threadIdx.x;
    if (idx >= BB * HH) return;
    oh[idx] = g_h[idx];
    oc[idx] = g_c[idx];
}

// ---------------- log-softmax ----------------
__global__ void __launch_bounds__(256) k_logsoftmax(float* __restrict__ logits) {
    int r = blockIdx.x;
    float* row = logits + (size_t)r * VV;
    float m = -1e30f, s = 0.f;
    for (int v = threadIdx.x; v < VV; v += 256) {
        float x = row[v];
        float nm = fmaxf(m, x);
        s = s * __expf(m - nm) + __expf(x - nm);
        m = nm;
    }
    __shared__ float sm_[256], ssum[256];
    sm_[threadIdx.x] = m; ssum[threadIdx.x] = s;
    __syncthreads();
    for (int w = 128; w > 0; w >>= 1) {
        if (threadIdx.x < w) {
            float m1 = sm_[threadIdx.x], s1 = ssum[threadIdx.x];
            float m2 = sm_[threadIdx.x + w], s2 = ssum[threadIdx.x + w];
            float nm = fmaxf(m1, m2);
            sm_[threadIdx.x] = nm;
            ssum[threadIdx.x] = s1 * __expf(m1 - nm) + s2 * __expf(m2 - nm);
        }
        __syncthreads();
    }
    float lse = sm_[0] + __logf(ssum[0]);
    for (int v = threadIdx.x; v < VV; v += 256) row[v] -= lse;
}

// ---------------- host ----------------
static void launch_gemm_t(const float* A, const float* W, const float* bias,
                          float* C, int M, int N, int K) {
    dim3 grid(N / 64, M / 64);
    k_gemm_t<<<grid, 128, SMEM_DYN>>>(A, W, bias, C, M, N, K);
}

extern "C" void kernel_launch(void* const* d_in, const int* in_sizes, int n_in,
                              void* d_out, int out_size) {
    (void)in_sizes; (void)n_in; (void)out_size;
    const float* enc    = (const float*)d_in[0];
    const float* encH   = (const float*)d_in[1];
    const float* encC   = (const float*)d_in[2];
    const int*   target = (const int*)d_in[4];
    const float* emb    = (const float*)d_in[5];
    const float* W1     = (const float*)d_in[6];
    const float* b1     = (const float*)d_in[7];
    const float* W2     = (const float*)d_in[8];
    const float* b2     = (const float*)d_in[9];
    const float* Vw     = (const float*)d_in[10];
    const float* Vb     = (const float*)d_in[11];
    const float* Wih    = (const float*)d_in[12];
    const float* Whh    = (const float*)d_in[13];
    const float* bih    = (const float*)d_in[14];
    const float* bhh    = (const float*)d_in[15];
    const float* outW   = (const float*)d_in[16];
    const float* outb   = (const float*)d_in[17];
    const float* br1W   = (const float*)d_in[18];
    const float* br1b   = (const float*)d_in[19];
    const float* br2W   = (const float*)d_in[20];
    const float* br2b   = (const float*)d_in[21];

    float* out = (float*)d_out;
    float* out_logp = out;
    float* out_h    = out + (size_t)BB * TT * VV;
    float* out_c    = out_h + BB * HH;
    float* out_attn = out_c + BB * HH;

    static bool attr_done = false;
    if (!attr_done) {
        cudaFuncSetAttribute(k_gemm_t, cudaFuncAttributeMaxDynamicSharedMemorySize, (int)SMEM_DYN);
        cudaFuncSetAttribute(k_gates,  cudaFuncAttributeMaxDynamicSharedMemorySize, (int)SMEM_DYN);
        attr_done = true;
    }

    void *pboutW, *pkeys, *pqw1, *ph, *pc, *pHabf, *pW1t, *prW, *prA, *pembA, *pembE, *pWihE, *pgbiasp, *phtf;
    cudaGetSymbolAddress(&pboutW, g_boutW);
    cudaGetSymbolAddress(&pkeys, g_keys);
    cudaGetSymbolAddress(&pqw1, g_qw1);
    cudaGetSymbolAddress(&ph, g_h);
    cudaGetSymbolAddress(&pc, g_c);
    cudaGetSymbolAddress(&pHabf, g_Habf);
    cudaGetSymbolAddress(&pW1t, g_W1t);
    cudaGetSymbolAddress(&prW, g_rW);
    cudaGetSymbolAddress(&prA, g_rA);
    cudaGetSymbolAddress(&pembA, g_embA);
    cudaGetSymbolAddress(&pembE, g_embE);
    cudaGetSymbolAddress(&pWihE, g_WihE);
    cudaGetSymbolAddress(&pgbiasp, g_gbiasp);
    cudaGetSymbolAddress(&phtf, g_htf);

    // ---- prep ----
    k_cvt<<<4096, 256>>>(outW, (__nv_bfloat16*)pboutW, (size_t)VV * HH);
    k_wcat2<<<4096, 256>>>(Wih, Whh);
    k_wembE<<<4096, 256>>>(Wih);
    k_gbiasp<<<(G4 + 255) / 256, 256>>>(bih, bhh);
    k_embA<<<2048, 256>>>(emb, target);
    k_round<<<1024, 256>>>(W1, (float*)pW1t, (size_t)HH * HH);

    // E = embA @ WihE^T + gbias_perm   (M=2048, N=4096, K=1024)
    launch_gemm_t((float*)pembA, (float*)pWihE, (float*)pgbiasp, (float*)pembE,
                  TT * BB, G4, HH);

    // ---- bridge + keys ----
    k_round<<<256, 256>>>(encH, (float*)prA, (size_t)BB * HH);
    k_round<<<1024, 256>>>(br1W, (float*)prW, (size_t)HH * HH);
    launch_gemm_t((float*)prA, (float*)prW, br1b, (float*)ph, BB, HH, HH);

    k_round<<<256, 256>>>(encC, (float*)prA, (size_t)BB * HH);
    k_round<<<1024, 256>>>(br2W, (float*)prW, (size_t)HH * HH);
    launch_gemm_t((float*)prA, (float*)prW, br2b, (float*)pc, BB, HH, HH);

    k_round<<<512, 256>>>(enc, (float*)prA, (size_t)SS * HH);   // encoder_outputs[0]
    k_round<<<1024, 256>>>(W2, (float*)prW, (size_t)HH * HH);
    launch_gemm_t((float*)prA, (float*)prW, b2, (float*)pkeys, SS, HH, HH);

    k_seed<<<BB * HH / 256, 256>>>();

    // ---- recurrent steps ----
    for (int t = 0; t < TT; t++) {
        launch_gemm_t((float*)phtf, (float*)pW1t, b1, (float*)pqw1, BB, HH, HH);
        k_attn<<<BB, 256>>>(enc, Vw, Vb, out_attn, t);
        k_gates<<<G4 / 64, 128, SMEM_DYN>>>(t);
    }

    k_copyhc<<<BB * HH / 256, 256>>>(out_h, out_c);

    // ---- logits + log-softmax ----
    {
        dim3 grid(VV / 64, BB * TT / 64);
        k_gemm<<<grid, 128>>>((__nv_bfloat16*)pHabf, (__nv_bfloat16*)pboutW, outb,
                              out_logp, BB * TT, VV, HH);
    }
    k_logsoftmax<<<BB * TT, 256>>>(out_logp);
}